// round 16
// baseline (speedup 1.0000x reference)
#include <cuda_runtime.h>
#include <math.h>
#include <cstdint>

#define CLS 8
#define NT 256
#define HIDN 256
#define ENCLEN 16
#define DECLEN 25
#define NV 28
#define ROWS 128            // gate rows per CTA (4 gates x 32 cells)

__device__ __forceinline__ float sigf(float x) {
    return __fdividef(1.0f, 1.0f + __expf(-x));
}
// packed dual-fp32 FMA: d = a*b + d (two independent IEEE fp32 lanes)
__device__ __forceinline__ void ffma2(unsigned long long& d,
                                      unsigned long long a, unsigned long long b) {
    asm("fma.rn.f32x2 %0, %1, %2, %3;" : "=l"(d) : "l"(a), "l"(b), "l"(d));
}
__device__ __forceinline__ float f2lo(unsigned long long v) {
    return __uint_as_float((unsigned)v);
}
__device__ __forceinline__ float f2hi(unsigned long long v) {
    return __uint_as_float((unsigned)(v >> 32));
}
__device__ __forceinline__ uint32_t smem_u32(const void* p) {
    return (uint32_t)__cvta_generic_to_shared(p);
}
__device__ __forceinline__ uint32_t mapa_rank(uint32_t laddr, int rk) {
    uint32_t ra;
    asm("mapa.shared::cluster.u32 %0, %1, %2;" : "=r"(ra) : "r"(laddr), "r"(rk));
    return ra;
}
__device__ __forceinline__ void st_async_f32(uint32_t ra_data, float v, uint32_t ra_mbar) {
    asm volatile(
        "st.async.weak.shared::cluster.mbarrier::complete_tx::bytes.b32 [%0], %1, [%2];"
        :: "r"(ra_data), "r"(__float_as_uint(v)), "r"(ra_mbar) : "memory");
}
__device__ __forceinline__ void mbar_init(uint32_t laddr, unsigned cnt) {
    asm volatile("mbarrier.init.shared.b64 [%0], %1;" :: "r"(laddr), "r"(cnt) : "memory");
}
__device__ __forceinline__ void mbar_expect(uint32_t laddr, unsigned bytes) {
    asm volatile("mbarrier.arrive.expect_tx.shared.b64 _, [%0], %1;"
                 :: "r"(laddr), "r"(bytes) : "memory");
}
__device__ __forceinline__ void mbar_wait(uint32_t laddr, unsigned parity) {
    unsigned done;
    asm volatile(
        "{\n\t.reg .pred p;\n\t"
        "mbarrier.try_wait.parity.acquire.cta.shared::cta.b64 p, [%1], %2;\n\t"
        "selp.b32 %0, 1, 0, p;\n\t}"
        : "=r"(done) : "r"(laddr), "r"(parity) : "memory");
    if (!done) {
        asm volatile(
            "{\n\t.reg .pred P1;\n\t"
            "WL_%=:\n\t"
            "mbarrier.try_wait.parity.acquire.cta.shared::cta.b64 P1, [%0], %1, 0x989680;\n\t"
            "@P1 bra.uni WD_%=;\n\t"
            "bra.uni WL_%=;\n\t"
            "WD_%=:\n\t}"
            :: "r"(laddr), "r"(parity) : "memory");
    }
}
__device__ __forceinline__ void cluster_sync_() {
    asm volatile("barrier.cluster.arrive.aligned;" ::: "memory");
    asm volatile("barrier.cluster.wait.aligned;" ::: "memory");
}

__global__ void __launch_bounds__(NT) __cluster_dims__(CLS, 1, 1) vae_kernel(
    const int* __restrict__ data, const int* __restrict__ data_c, const int* __restrict__ target_c,
    const float* __restrict__ cond_emb, const float* __restrict__ enc_emb,
    const float* __restrict__ enc_Wih, const float* __restrict__ enc_Whh,
    const float* __restrict__ enc_bih, const float* __restrict__ enc_bhh,
    const float* __restrict__ hmu_W, const float* __restrict__ hmu_b,
    const float* __restrict__ cmu_W, const float* __restrict__ cmu_b,
    const float* __restrict__ fc1_W, const float* __restrict__ fc1_b,
    const float* __restrict__ fc2_W, const float* __restrict__ fc2_b,
    const float* __restrict__ dec_emb, const float* __restrict__ dec_Wih,
    const float* __restrict__ dec_Whh, const float* __restrict__ dec_bih,
    const float* __restrict__ dec_bhh, const float* __restrict__ out_W,
    const float* __restrict__ out_b,
    float* __restrict__ out, int out_size)
{
    extern __shared__ __align__(16) float xbuf[];      // 28KB staging
    __shared__ __align__(16) float hbuf[2][HIDN];
    __shared__ __align__(16) float cbuf[HIDN];
    __shared__ __align__(8) unsigned long long mbars[2];
    __shared__ float PE_s[ENCLEN * ROWS];
    __shared__ float PD_s[NV * ROWS];
    __shared__ float logits_s[32];
    __shared__ float outb_s[NV];
    __shared__ float mu_s[40], cmu_s[40];
    __shared__ int toks_s[ENCLEN];

    const int tid = threadIdx.x;
    const int crank = blockIdx.x;       // grid == one 8-CTA cluster
    const int w = tid >> 5, l = tid & 31;
    const int rr = l >> 1;              // row-in-warp 0..15
    const int hf = l & 1;               // k-half (128 floats each)
    const int gate = rr >> 2, cj = rr & 3;
    const int lr = w * 16 + rr;         // local row 0..127
    const int G = gate * HIDN + 32 * crank + 4 * w + cj;   // global gate row
    const bool prod = (rr < 4) && (hf == 0);
    const int pcell_g = 32 * crank + 4 * w + rr;           // valid when prod
    const int r3 = tid >> 3, q3 = tid & 7;
    const int r3c = (r3 < NV) ? r3 : 0;

    const uint32_t mb_l0 = smem_u32(&mbars[0]);
    const uint32_t mb_l1 = smem_u32(&mbars[1]);
    if (tid == 0) { mbar_init(mb_l0, 1); mbar_init(mb_l1, 1); }

    // ---- h0 = zeros(248) ++ cond_emb[data_c] ----
    {
        int dc = data_c[0];
        hbuf[0][tid] = (tid < HIDN - 8) ? 0.0f : cond_emb[dc * 8 + (tid - (HIDN - 8))];
        if (tid < ENCLEN) toks_s[tid] = data[tid];
        if (tid < NV) outb_s[tid] = out_b[tid];
    }
    __syncthreads();
    cluster_sync_();    // mbars initialized cluster-wide before any st.async

    // ---- xbuf := encoder embedding rows ----
    for (int idx = tid; idx < ENCLEN * (HIDN / 4); idx += NT) {
        int t = idx >> 6, c2 = idx & 63;
        ((float4*)xbuf)[idx] = ((const float4*)enc_emb)[toks_s[t] * 64 + c2];
    }
    __syncthreads();

    const float biasE = enc_bih[G] + enc_bhh[G];
    const float biasD = dec_bih[G] + dec_bhh[G];

    // ---- register weight slice (one array, repurposed per phase) ----
    ulonglong2 w2[32];   // half-row: 128 floats = 32 x (2 x f32x2)

    // ---- PE: enc_bias + enc_Wih @ x_t (f32x2) ----
    {
        const ulonglong2* src = (const ulonglong2*)(enc_Wih + (size_t)G * HIDN) + hf * 32;
        #pragma unroll
        for (int k = 0; k < 32; k++) w2[k] = src[k];
        for (int t = 0; t < ENCLEN; t++) {
            const ulonglong2* xv = (const ulonglong2*)(xbuf + t * HIDN) + hf * 32;
            unsigned long long a0 = 0ULL, a1 = 0ULL;
            #pragma unroll
            for (int k = 0; k < 32; k++) {
                ulonglong2 x = xv[k];
                ffma2(a0, w2[k].x, x.x);
                ffma2(a1, w2[k].y, x.y);
            }
            float acc = (f2lo(a0) + f2hi(a0)) + (f2lo(a1) + f2hi(a1));
            acc += __shfl_xor_sync(~0u, acc, 1);
            if (hf == 0) PE_s[t * ROWS + lr] = acc + biasE;
        }
    }
    __syncthreads();

    // ---- xbuf := relu(dec_emb) (PD inputs for the encoder bubbles) ----
    for (int idx = tid; idx < NV * (HIDN / 4); idx += NT) {
        float4 v = ((const float4*)dec_emb)[idx];
        v.x = fmaxf(v.x, 0.0f); v.y = fmaxf(v.y, 0.0f);
        v.z = fmaxf(v.z, 0.0f); v.w = fmaxf(v.w, 0.0f);
        ((float4*)xbuf)[idx] = v;
    }
    // ---- w2 := enc_Whh (encoder recurrent weights) ----
    {
        const ulonglong2* src = (const ulonglong2*)(enc_Whh + (size_t)G * HIDN) + hf * 32;
        #pragma unroll
        for (int k = 0; k < 32; k++) w2[k] = src[k];
    }
    __syncthreads();

    // ---- producer DSMEM bases (mapa once; derive targets by offset) ----
    uint32_t rkb[CLS];
    uint32_t dh0 = 0, dh1 = 0, dmb0 = 0, dmb1 = 0, dcc = 0;
    if (prod) {
        uint32_t base0 = smem_u32(&hbuf[0][0]);
        #pragma unroll
        for (int rk = 0; rk < CLS; rk++) rkb[rk] = mapa_rank(base0, rk);
        dh0 = smem_u32(&hbuf[0][pcell_g]) - base0;
        dh1 = smem_u32(&hbuf[1][pcell_g]) - base0;
        dmb0 = mb_l0 - base0;
        dmb1 = mb_l1 - base0;
        dcc = smem_u32(&cbuf[pcell_g]) - base0;
    }
    float c = prod ? hbuf[0][pcell_g] : 0.0f;
    int ph0 = 0, ph1 = 0;

    // step: gates from hbuf[(e-1)&1] via f32x2; publish h (and c) via st.async
    auto step_compute_publish = [&](const float* P, int e, bool emit_c) {
        const int ob = e & 1;
        if (tid == 0) mbar_expect(ob ? mb_l1 : mb_l0, emit_c ? 2048u : 1024u);
        const ulonglong2* hv = (const ulonglong2*)hbuf[ob ^ 1] + hf * 32;
        unsigned long long a0 = 0ULL, a1 = 0ULL;
        #pragma unroll
        for (int k = 0; k < 32; k++) {
            ulonglong2 x = hv[k];
            ffma2(a0, w2[k].x, x.x);
            ffma2(a1, w2[k].y, x.y);
        }
        float acc = (f2lo(a0) + f2hi(a0)) + (f2lo(a1) + f2hi(a1));
        acc += __shfl_xor_sync(~0u, acc, 1);
        float val = acc + P[lr];
        float a = (gate == 2) ? tanhf(val) : sigf(val);
        float iv = __shfl_sync(~0u, a, 2 * cj);
        float fv = __shfl_sync(~0u, a, 2 * (4 + cj));
        float gv = __shfl_sync(~0u, a, 2 * (8 + cj));
        float ov = __shfl_sync(~0u, a, 2 * (12 + cj));
        if (prod) {
            float nc = fv * c + iv * gv;
            c = nc;
            float h = ov * tanhf(nc);
            uint32_t dh = ob ? dh1 : dh0;
            uint32_t dmb = ob ? dmb1 : dmb0;
            #pragma unroll
            for (int rk = 0; rk < CLS; rk++)
                st_async_f32(rkb[rk] + dh, h, rkb[rk] + dmb);
            if (emit_c) {
                #pragma unroll
                for (int rk = 0; rk < CLS; rk++)
                    st_async_f32(rkb[rk] + dcc, c, rkb[rk] + dmb);
            }
        }
    };
    auto step_wait = [&](int e) {
        if (e & 1) { mbar_wait(mb_l1, (unsigned)ph1); ph1 ^= 1; }
        else       { mbar_wait(mb_l0, (unsigned)ph0); ph0 ^= 1; }
    };

    // ========== encoder (e=1..16); PD GEMVs hidden in the exchange bubbles ====
    // PD weights stream from global (no second register array -> no spills).
    for (int t = 0; t < ENCLEN; t++) {
        step_compute_publish(PE_s + t * ROWS, t + 1, t == ENCLEN - 1);
        int v0 = (t < 12) ? 2 * t : 24 + (t - 12);
        int nvv = (t < 12) ? 2 : 1;
        const ulonglong2* gw = (const ulonglong2*)(dec_Wih + (size_t)G * HIDN) + hf * 32;
        for (int j = 0; j < nvv; j++) {
            int v = v0 + j;
            const ulonglong2* xv = (const ulonglong2*)(xbuf + v * HIDN) + hf * 32;
            unsigned long long a0 = 0ULL, a1 = 0ULL;
            #pragma unroll
            for (int k = 0; k < 32; k++) {
                ulonglong2 wv = gw[k];
                ulonglong2 x = xv[k];
                ffma2(a0, wv.x, x.x);
                ffma2(a1, wv.y, x.y);
            }
            float acc = (f2lo(a0) + f2hi(a0)) + (f2lo(a1) + f2hi(a1));
            acc += __shfl_xor_sync(~0u, acc, 1);
            if (hf == 0) PD_s[v * ROWS + lr] = acc + biasD;
        }
        step_wait(t + 1);
    }

    // ================= latent transform (replicated per CTA) =================
    {
        float a1 = 0.0f, a2 = 0.0f;
        const float* whm = hmu_W + r3 * HIDN + q3 * 32;
        const float* wcm = cmu_W + r3 * HIDN + q3 * 32;
        #pragma unroll
        for (int k = 0; k < 32; k++) {
            a1 += whm[k] * hbuf[0][q3 * 32 + k];     // h16 (e=16 -> buffer 0)
            a2 += wcm[k] * cbuf[q3 * 32 + k];        // cT
        }
        a1 += __shfl_xor_sync(~0u, a1, 1); a1 += __shfl_xor_sync(~0u, a1, 2); a1 += __shfl_xor_sync(~0u, a1, 4);
        a2 += __shfl_xor_sync(~0u, a2, 1); a2 += __shfl_xor_sync(~0u, a2, 2); a2 += __shfl_xor_sync(~0u, a2, 4);
        if (q3 == 0) { mu_s[r3] = a1 + hmu_b[r3]; cmu_s[r3] = a2 + cmu_b[r3]; }
        if (tid < 8) {
            float tc = cond_emb[target_c[0] * 8 + tid];
            mu_s[32 + tid] = tc;
            cmu_s[32 + tid] = tc;
        }
        __syncthreads();   // PD bubbles + hbuf0/cbuf reads complete

        // xbuf := out_W for decoder logits (PD done reading xbuf)
        for (int idx = tid; idx < NV * (HIDN / 4); idx += NT)
            ((float4*)xbuf)[idx] = ((const float4*)out_W)[idx];

        float d1 = fc1_b[tid], d2 = fc2_b[tid];
        const float* w1 = fc1_W + tid * 40;
        const float* w2p = fc2_W + tid * 40;
        #pragma unroll
        for (int k = 0; k < 40; k++) { d1 += w1[k] * mu_s[k]; d2 += w2p[k] * cmu_s[k]; }
        __syncthreads();
        hbuf[0][tid] = d1;   // decoder h0 (identical in all CTAs; local write)
        cbuf[tid] = d2;      // decoder c0
        __syncthreads();
        if (prod) c = cbuf[pcell_g];
    }

    // ---- w2 := dec_Whh ----
    {
        const ulonglong2* src = (const ulonglong2*)(dec_Whh + (size_t)G * HIDN) + hf * 32;
        #pragma unroll
        for (int k = 0; k < 32; k++) w2[k] = src[k];
    }
    __syncthreads();

    // ================= decoder (e = 17..41), greedy =================
    int tok = 0;  // SOS
    for (int t = 0; t < DECLEN; t++) {
        int e = ENCLEN + 1 + t;
        step_compute_publish(PD_s + tok * ROWS, e, false);
        step_wait(e);
        const int ob = e & 1;

        // logits = h @ out_W^T + out_b (f32x2).
        // Row = 256 floats = 64 ulonglong2; 8 threads/row, 8 ulonglong2
        // (32 floats) per thread. FIXED from R15 (was half-row/overlapping).
        unsigned long long a0 = 0ULL, a1 = 0ULL;
        {
            const ulonglong2* wv = (const ulonglong2*)xbuf + r3c * 64 + q3 * 8;
            const ulonglong2* hv2 = (const ulonglong2*)hbuf[ob] + q3 * 8;
            #pragma unroll
            for (int k = 0; k < 8; k++) {
                ulonglong2 ww = wv[k];
                ulonglong2 hh = hv2[k];
                ffma2(a0, ww.x, hh.x);
                ffma2(a1, ww.y, hh.y);
            }
        }
        float la = (f2lo(a0) + f2hi(a0)) + (f2lo(a1) + f2hi(a1));
        la += __shfl_xor_sync(~0u, la, 1);
        la += __shfl_xor_sync(~0u, la, 2);
        la += __shfl_xor_sync(~0u, la, 4);
        if (q3 == 0 && r3 < NV) {
            float lg = la + outb_s[r3];
            logits_s[r3] = lg;
            if (crank == 0) out[t * NV + r3] = lg;
        }
        __syncthreads();
        // per-warp argmax (logits_s stable until well after every warp's read)
        {
            float v = (l < NV) ? logits_s[l] : -1e30f;
            int idx = l;
            #pragma unroll
            for (int off = 1; off < 32; off <<= 1) {
                float ov2 = __shfl_xor_sync(~0u, v, off);
                int oi = __shfl_xor_sync(~0u, idx, off);
                if (ov2 > v || (ov2 == v && oi < idx)) { v = ov2; idx = oi; }
            }
            tok = idx;
            if (crank == 0 && tid == 0 && out_size >= DECLEN * NV + DECLEN)
                out[DECLEN * NV + t] = (float)idx;
        }
    }

    // no CTA exits while peers may still st.async into its smem
    cluster_sync_();
}

extern "C" void kernel_launch(void* const* d_in, const int* in_sizes, int n_in,
                              void* d_out, int out_size) {
    (void)in_sizes; (void)n_in;
    size_t smem = (size_t)(NV * HIDN) * sizeof(float);   // 28KB dynamic
    cudaFuncSetAttribute(vae_kernel, cudaFuncAttributeMaxDynamicSharedMemorySize, (int)smem);
    vae_kernel<<<CLS, NT, smem>>>(
        (const int*)d_in[0], (const int*)d_in[1], (const int*)d_in[2],
        (const float*)d_in[3], (const float*)d_in[4],
        (const float*)d_in[5], (const float*)d_in[6],
        (const float*)d_in[7], (const float*)d_in[8],
        (const float*)d_in[9], (const float*)d_in[10],
        (const float*)d_in[11], (const float*)d_in[12],
        (const float*)d_in[13], (const float*)d_in[14],
        (const float*)d_in[15], (const float*)d_in[16],
        (const float*)d_in[17], (const float*)d_in[18],
        (const float*)d_in[19], (const float*)d_in[20],
        (const float*)d_in[21], (const float*)d_in[22],
        (const float*)d_in[23],
        (float*)d_out, out_size);
}